// round 3
// baseline (speedup 1.0000x reference)
#include <cuda_runtime.h>
#include <cuda_bf16.h>
#include <cstdint>

// NLTKHierarchicalSoftmax: B=4096, NHID=512, BR=32, DEPTH=3
// Round 3: fused single-CTA counting sort + FFMA2/LDS128 work kernel.
//   Warp processes a run of <=8 samples sharing one W node.
//   lane = output column; W pairs (2 h) packed in f32x2 regs;
//   x staged in smem, read back as broadcast ld.shared.v2.b64;
//   inner op: fma.rn.f32x2 (2 MACs/lane/instr), two partial sums per acc.

#define FULL 0xffffffffu
#define NHID 512
#define BR 32
#define NB2 1024
#define BTOT 4096
#define WNODE (NHID*BR)

__device__ int g_off[NB2 + 1];
__device__ int g_sorted[BTOT];
__device__ float g_p[3 * BTOT];

// ---------------- fused counting sort (single CTA, 1024 threads) -------------
__global__ void __launch_bounds__(NB2) k_sort(const int* __restrict__ labels, int B)
{
    __shared__ int cnt[NB2];
    __shared__ int cur[NB2];
    int t = threadIdx.x;

    cnt[t] = 0;
    __syncthreads();
    for (int i = t; i < B; i += NB2)
        atomicAdd(&cnt[labels[i] >> 5], 1);
    __syncthreads();

    // Hillis-Steele inclusive scan
    int v = cnt[t];
    int run = v;
    #pragma unroll
    for (int off = 1; off < NB2; off <<= 1) {
        int u = (t >= off) ? cnt[t - off] : 0;
        __syncthreads();
        cnt[t] += u;
        __syncthreads();
    }
    int excl = cnt[t] - run;
    g_off[t] = excl;
    cur[t] = excl;
    if (t == NB2 - 1) g_off[NB2] = cnt[t];
    __syncthreads();

    for (int i = t; i < B; i += NB2) {
        int key = labels[i] >> 5;
        int pos = atomicAdd(&cur[key], 1);
        g_sorted[pos] = i;
    }
}

// ---------------- packed f32x2 helpers ---------------------------------------
typedef unsigned long long u64t;

__device__ __forceinline__ u64t ffma2(u64t a, u64t b, u64t c)
{
    u64t d;
    asm("fma.rn.f32x2 %0, %1, %2, %3;" : "=l"(d) : "l"(a), "l"(b), "l"(c));
    return d;
}
__device__ __forceinline__ u64t packf2(float lo, float hi)
{
    u64t d;
    asm("mov.b64 %0, {%1, %2};" : "=l"(d) : "f"(lo), "f"(hi));
    return d;
}
__device__ __forceinline__ float2 unpackf2(u64t v)
{
    float2 r;
    asm("mov.b64 {%0, %1}, %2;" : "=f"(r.x), "=f"(r.y) : "l"(v));
    return r;
}

// ---------------- work kernel -------------------------------------------------
// per-warp smem x tile: 8 samples x 128 h (one superchunk), 4KB/warp
#define WARPS_PER_CTA 8
__shared__ __align__(16) float xs_tile[WARPS_PER_CTA][8][128];

__device__ __forceinline__ void process_run(
    const float* __restrict__ x, const float* __restrict__ Wn,
    const int* bs, unsigned msk, const int* step,
    int lane, int wslot, float* __restrict__ pout)
{
    u64t acc2[8];
    #pragma unroll
    for (int s = 0; s < 8; s++) acc2[s] = 0ull;

    float (*xsm)[128] = xs_tile[wslot];

    #pragma unroll 1
    for (int sc = 0; sc < 4; sc++) {          // 4 superchunks of 128 h
        __syncwarp();
        // stage x: lane loads float4 per sample (coalesced 512B rows)
        #pragma unroll
        for (int s = 0; s < 8; s++) {
            const float4 xv = *(const float4*)(x + (size_t)bs[s] * NHID
                                               + sc * 128 + lane * 4);
            *(float4*)&xsm[s][lane * 4] = xv;
        }
        __syncwarp();

        #pragma unroll 1
        for (int sub = 0; sub < 4; sub++) {    // 32 h per subchunk
            const int h0 = sc * 128 + sub * 32;
            // W pairs for this lane's column: 16 f32x2 regs
            u64t wp[16];
            #pragma unroll
            for (int k = 0; k < 16; k++) {
                float wa = __ldg(Wn + (size_t)(h0 + 2 * k) * BR + lane);
                float wb = __ldg(Wn + (size_t)(h0 + 2 * k + 1) * BR + lane);
                wp[k] = packf2(wa, wb);
            }
            #pragma unroll
            for (int s = 0; s < 8; s++) {
                const ulonglong2* xrow =
                    (const ulonglong2*)&xsm[s][sub * 32];
                #pragma unroll
                for (int q = 0; q < 8; q++) {
                    ulonglong2 xq = xrow[q];     // LDS.128 broadcast: 4 x vals
                    acc2[s] = ffma2(xq.x, wp[2 * q], acc2[s]);
                    acc2[s] = ffma2(xq.y, wp[2 * q + 1], acc2[s]);
                }
            }
        }
    }

    // softmax per sample over 32 columns (lane = column)
    #pragma unroll
    for (int s = 0; s < 8; s++) {
        if (msk & (1u << s)) {
            float2 h = unpackf2(acc2[s]);
            float acc = h.x + h.y;
            float m = acc;
            #pragma unroll
            for (int o = 16; o > 0; o >>= 1)
                m = fmaxf(m, __shfl_xor_sync(FULL, m, o));
            float e = __expf(acc - m);
            float sum = e;
            #pragma unroll
            for (int o = 16; o > 0; o >>= 1)
                sum += __shfl_xor_sync(FULL, sum, o);
            float est = __shfl_sync(FULL, e, step[s]);
            if (lane == 0) pout[bs[s]] = est / sum;
        }
    }
    __syncwarp();
}

__global__ void __launch_bounds__(32 * WARPS_PER_CTA) k_work(
    const float* __restrict__ x, const int* __restrict__ labels,
    const float* __restrict__ W)
{
    int gw = (blockIdx.x * blockDim.x + threadIdx.x) >> 5;
    int lane = threadIdx.x & 31;
    int wslot = (threadIdx.x >> 5);

    if (gw < 1024) {
        // levels 0 and 1: tiles of 8 consecutive sorted samples
        int level = gw >> 9;      // 0 or 1
        int tile = gw & 511;
        int s0 = tile * 8;

        int bs[8], step[8], node[8];
        #pragma unroll
        for (int s = 0; s < 8; s++) {
            bs[s] = __ldg(&g_sorted[s0 + s]);
            int lab = __ldg(&labels[bs[s]]);
            if (level == 0) { node[s] = 0;               step[s] = (lab >> 10) & 31; }
            else            { node[s] = 1 + (lab >> 10); step[s] = (lab >> 5) & 31; }
        }

        unsigned rem = 0xffu;
        while (rem) {
            int src = __ffs(rem) - 1;
            int n = node[src];
            unsigned msk = 0;
            #pragma unroll
            for (int s = 0; s < 8; s++)
                if (node[s] == n) msk |= 1u << s;
            process_run(x, W + (size_t)n * WNODE, bs, msk, step, lane, wslot,
                        g_p + level * BTOT);
            rem &= ~msk;
        }
    } else if (gw < 1024 + NB2) {
        // level 2: one warp per bucket (node = 33 + bucket)
        int w = gw - 1024;
        int beg = __ldg(&g_off[w]);
        int end = __ldg(&g_off[w + 1]);
        if (beg == end) return;
        const float* Wn = W + (size_t)(33 + w) * WNODE;

        for (int t = beg; t < end; t += 8) {
            int G = min(8, end - t);
            int bs[8], step[8];
            #pragma unroll
            for (int s = 0; s < 8; s++) {
                int idx = t + ((s < G) ? s : (G - 1));   // replicate last
                int b = __ldg(&g_sorted[idx]);
                bs[s] = b;
                step[s] = __ldg(&labels[b]) & 31;
            }
            unsigned msk = (G >= 8) ? 0xffu : ((1u << G) - 1u);
            process_run(x, Wn, bs, msk, step, lane, wslot, g_p + 2 * BTOT);
        }
    }
}

__global__ void k_final(float* __restrict__ out, int B)
{
    int i = blockIdx.x * blockDim.x + threadIdx.x;
    if (i < B) out[i] = g_p[i] * g_p[BTOT + i] * g_p[2 * BTOT + i];
}

extern "C" void kernel_launch(void* const* d_in, const int* in_sizes, int n_in,
                              void* d_out, int out_size)
{
    const float* x      = (const float*)d_in[0];
    const int*   labels = (const int*)d_in[1];
    const float* W      = (const float*)d_in[2];
    float* out = (float*)d_out;

    int B = in_sizes[1];  // 4096

    k_sort<<<1, NB2>>>(labels, B);

    int warps = 1024 + NB2;               // 2048
    int threads = 32 * WARPS_PER_CTA;     // 256
    int blocks = (warps * 32 + threads - 1) / threads;
    k_work<<<blocks, threads>>>(x, labels, W);

    k_final<<<(B + 255) / 256, 256>>>(out, B);
}

// round 4
// speedup vs baseline: 1.6101x; 1.6101x over previous
#include <cuda_runtime.h>
#include <cuda_bf16.h>
#include <cstdint>

// NLTKHierarchicalSoftmax: B=4096, NHID=512, BR=32, DEPTH=3
// Round 4: shuffle-scan sort + pipelined FFMA2 work kernel.
//   - W double-buffered in regs, prefetched one 16-h subchunk ahead (hides L2 lat)
//   - FMA order q-outer/s-inner: independent accumulator chains
//   - level 2 uses TS=4 runs for small tails (less padded compute)

#define FULL 0xffffffffu
#define NHID 512
#define BR 32
#define NB2 1024
#define BTOT 4096
#define WNODE (NHID*BR)

__device__ int g_off[NB2 + 1];
__device__ int g_sorted[BTOT];
__device__ float g_p[3 * BTOT];

// ---------------- packed f32x2 helpers ---------------------------------------
typedef unsigned long long u64t;

__device__ __forceinline__ u64t ffma2(u64t a, u64t b, u64t c)
{
    u64t d;
    asm("fma.rn.f32x2 %0, %1, %2, %3;" : "=l"(d) : "l"(a), "l"(b), "l"(c));
    return d;
}
__device__ __forceinline__ u64t packf2(float lo, float hi)
{
    u64t d;
    asm("mov.b64 %0, {%1, %2};" : "=l"(d) : "f"(lo), "f"(hi));
    return d;
}
__device__ __forceinline__ float2 unpackf2(u64t v)
{
    float2 r;
    asm("mov.b64 {%0, %1}, %2;" : "=f"(r.x), "=f"(r.y) : "l"(v));
    return r;
}

// ---------------- counting sort (single CTA, shuffle scan) -------------------
__global__ void __launch_bounds__(NB2) k_sort(const int* __restrict__ labels, int B)
{
    __shared__ int cnt[NB2];
    __shared__ int cur[NB2];
    __shared__ int wsum[32];
    int t = threadIdx.x;
    int lane = t & 31;
    int warp = t >> 5;

    cnt[t] = 0;
    __syncthreads();
    for (int i = t; i < B; i += NB2)
        atomicAdd(&cnt[labels[i] >> 5], 1);
    __syncthreads();

    int v = cnt[t];
    int inc = v;
    #pragma unroll
    for (int o = 1; o < 32; o <<= 1) {
        int u = __shfl_up_sync(FULL, inc, o);
        if (lane >= o) inc += u;
    }
    if (lane == 31) wsum[warp] = inc;
    __syncthreads();
    if (t < 32) {
        int wv = wsum[t];
        int wi = wv;
        #pragma unroll
        for (int o = 1; o < 32; o <<= 1) {
            int u = __shfl_up_sync(FULL, wi, o);
            if (t >= o) wi += u;
        }
        wsum[t] = wi - wv;   // exclusive prefix of warp totals
    }
    __syncthreads();

    int excl = wsum[warp] + inc - v;
    g_off[t] = excl;
    cur[t] = excl;
    if (t == NB2 - 1) g_off[NB2] = excl + v;
    __syncthreads();

    for (int i = t; i < B; i += NB2) {
        int key = labels[i] >> 5;
        int pos = atomicAdd(&cur[key], 1);
        g_sorted[pos] = i;
    }
}

// ---------------- pipelined run processor -------------------------------------
// lane = output column. 32 subchunks of 16 h; W prefetched one subchunk ahead.
template<int TS>
__device__ __forceinline__ void process_run(
    const float* __restrict__ x, const float* __restrict__ Wn,
    const int* bs, unsigned msk, const int* step,
    int lane, float (*xsm)[128], float* __restrict__ pout)
{
    u64t acc2[TS];
    #pragma unroll
    for (int s = 0; s < TS; s++) acc2[s] = 0ull;

    float wr[2][16];
    #pragma unroll
    for (int k = 0; k < 16; k++)
        wr[0][k] = __ldg(Wn + k * BR + lane);

    #pragma unroll 1
    for (int sc = 0; sc < 4; sc++) {            // 4 superchunks of 128 h
        __syncwarp();
        #pragma unroll
        for (int s = 0; s < TS; s++) {
            float4 xv = *(const float4*)(x + (size_t)bs[s] * NHID
                                         + sc * 128 + lane * 4);
            *(float4*)&xsm[s][lane * 4] = xv;
        }
        __syncwarp();

        #pragma unroll
        for (int sub = 0; sub < 8; sub++) {     // 8 subchunks of 16 h
            const int curb = sub & 1;           // static after unroll
            const int subg = sc * 8 + sub;
            if (subg + 1 < 32) {                // prefetch next subchunk W
                int h0 = (subg + 1) * 16;
                #pragma unroll
                for (int k = 0; k < 16; k++)
                    wr[curb ^ 1][k] = __ldg(Wn + (h0 + k) * BR + lane);
            }
            u64t wp[8];
            #pragma unroll
            for (int k = 0; k < 8; k++)
                wp[k] = packf2(wr[curb][2 * k], wr[curb][2 * k + 1]);

            #pragma unroll
            for (int q = 0; q < 4; q++) {       // 4 h per q
                #pragma unroll
                for (int s = 0; s < TS; s++) {  // independent chains
                    ulonglong2 xq =
                        *(const ulonglong2*)&xsm[s][sub * 16 + q * 4];
                    acc2[s] = ffma2(xq.x, wp[2 * q], acc2[s]);
                    acc2[s] = ffma2(xq.y, wp[2 * q + 1], acc2[s]);
                }
            }
        }
    }

    // softmax per sample over 32 columns (lane = column)
    #pragma unroll
    for (int s = 0; s < TS; s++) {
        if (msk & (1u << s)) {
            float2 h = unpackf2(acc2[s]);
            float acc = h.x + h.y;
            float m = acc;
            #pragma unroll
            for (int o = 16; o > 0; o >>= 1)
                m = fmaxf(m, __shfl_xor_sync(FULL, m, o));
            float e = __expf(acc - m);
            float sum = e;
            #pragma unroll
            for (int o = 16; o > 0; o >>= 1)
                sum += __shfl_xor_sync(FULL, sum, o);
            float est = __shfl_sync(FULL, e, step[s]);
            if (lane == 0) pout[bs[s]] = est / sum;
        }
    }
    __syncwarp();
}

// ---------------- work kernel -------------------------------------------------
#define WARPS_PER_CTA 8

__global__ void __launch_bounds__(32 * WARPS_PER_CTA, 2) k_work(
    const float* __restrict__ x, const int* __restrict__ labels,
    const float* __restrict__ W, int B)
{
    __shared__ __align__(16) float xs_tile[WARPS_PER_CTA][8][128];

    int gw = (blockIdx.x * blockDim.x + threadIdx.x) >> 5;
    int lane = threadIdx.x & 31;
    float (*xsm)[128] = xs_tile[threadIdx.x >> 5];

    const int nl0 = (B + 7) / 8;   // 512
    const int nl1 = nl0;           // 512

    if (gw < nl0) {
        // level 0: node 0 for everyone; natural sample order (no indirection)
        int s0 = gw * 8;
        int bs[8], step[8];
        unsigned msk = 0;
        #pragma unroll
        for (int s = 0; s < 8; s++) {
            int b = s0 + s;
            bool ok = (b < B);
            if (!ok) b = B - 1;
            bs[s] = b;
            step[s] = (__ldg(&labels[b]) >> 10) & 31;
            if (ok) msk |= 1u << s;
        }
        process_run<8>(x, W, bs, msk, step, lane, xsm, g_p);
    } else if (gw < nl0 + nl1) {
        // level 1: tiles of 8 consecutive sorted samples; node = 1 + (lab>>10)
        int s0 = (gw - nl0) * 8;
        int bs[8], step[8], node[8];
        #pragma unroll
        for (int s = 0; s < 8; s++) {
            int idx = s0 + s;
            if (idx >= B) idx = B - 1;
            int b = __ldg(&g_sorted[idx]);
            bs[s] = b;
            int lab = __ldg(&labels[b]);
            node[s] = 1 + (lab >> 10);
            step[s] = (lab >> 5) & 31;
        }
        unsigned valid = (s0 + 8 <= B) ? 0xffu : ((1u << (B - s0)) - 1u);
        unsigned rem = valid;
        while (rem) {
            int src = __ffs(rem) - 1;
            int n = node[src];
            unsigned msk = 0;
            #pragma unroll
            for (int s = 0; s < 8; s++)
                if (node[s] == n) msk |= 1u << s;
            msk &= valid;
            process_run<8>(x, W + (size_t)n * WNODE, bs, msk, step, lane, xsm,
                           g_p + BTOT);
            rem &= ~msk;
        }
    } else if (gw < nl0 + nl1 + NB2) {
        // level 2: one warp per bucket (node = 33 + bucket)
        int w = gw - nl0 - nl1;
        int beg = __ldg(&g_off[w]);
        int end = __ldg(&g_off[w + 1]);
        if (beg == end) return;
        const float* Wn = W + (size_t)(33 + w) * WNODE;

        int t = beg;
        while (end - t >= 5) {                       // big chunks: TS=8
            int G = min(8, end - t);
            int bs[8], step[8];
            #pragma unroll
            for (int s = 0; s < 8; s++) {
                int idx = t + ((s < G) ? s : (G - 1));
                int b = __ldg(&g_sorted[idx]);
                bs[s] = b;
                step[s] = __ldg(&labels[b]) & 31;
            }
            unsigned msk = (G >= 8) ? 0xffu : ((1u << G) - 1u);
            process_run<8>(x, Wn, bs, msk, step, lane, xsm, g_p + 2 * BTOT);
            t += G;
        }
        if (t < end) {                               // tail <=4: TS=4
            int G = end - t;
            int bs[4], step[4];
            #pragma unroll
            for (int s = 0; s < 4; s++) {
                int idx = t + ((s < G) ? s : (G - 1));
                int b = __ldg(&g_sorted[idx]);
                bs[s] = b;
                step[s] = __ldg(&labels[b]) & 31;
            }
            unsigned msk = (1u << G) - 1u;
            process_run<4>(x, Wn, bs, msk, step, lane, xsm, g_p + 2 * BTOT);
        }
    }
}

__global__ void k_final(float* __restrict__ out, int B)
{
    int i = blockIdx.x * blockDim.x + threadIdx.x;
    if (i < B) out[i] = g_p[i] * g_p[BTOT + i] * g_p[2 * BTOT + i];
}

extern "C" void kernel_launch(void* const* d_in, const int* in_sizes, int n_in,
                              void* d_out, int out_size)
{
    const float* x      = (const float*)d_in[0];
    const int*   labels = (const int*)d_in[1];
    const float* W      = (const float*)d_in[2];
    float* out = (float*)d_out;

    int B = in_sizes[1];  // 4096

    k_sort<<<1, NB2>>>(labels, B);

    int warps = (B + 7) / 8 * 2 + NB2;    // 2048
    int threads = 32 * WARPS_PER_CTA;     // 256
    int blocks = (warps * 32 + threads - 1) / threads;
    k_work<<<blocks, threads>>>(x, labels, W, B);

    k_final<<<(B + 255) / 256, 256>>>(out, B);
}